// round 14
// baseline (speedup 1.0000x reference)
#include <cuda_runtime.h>

#define N_NODES 10000
#define N_EDGES 320000
#define QUADS (N_EDGES / 4)
#define NB 148
#define NT 1024
#define NTHR (NB * NT)
#define BM_WORDS 320
#define DC 68       // P4 dot chunk: 148 blocks x 68 >= 10000
#define DC5 76      // P5' dot chunk: 132 blocks x 76 >= 10000
#define QPB 1082    // quads per block: 148*1082 >= 2*QUADS (last block partial)

// INVARIANT: accumulated scratch (CL*, bm*, D, sig) is ZERO at kernel entry
// and restored to ZERO before exit. g_RC is fully overwritten in P1 before any
// read. L1-cached __ldg of data written earlier in this launch is safe: L1 is
// flushed at launch boundaries, global stores/atomics don't allocate in L1,
// and no array is regular-loaded before its producer phase's barrier.
__device__ float2 g_CL1[N_NODES];      // {R1, R2}
__device__ float4 g_CL2[N_NODES];      // {R3, R5, R4, R6}
__device__ float2 g_CL3p[2][N_NODES];  // GSO0: {R7, R11}; GSO1: {R8, R12}  (lvl4 gathers)
__device__ float  g_CL3s[2][N_NODES];  // GSO0: R10;       GSO1: R9        (dot only)
__device__ float4 g_CL4[N_NODES];      // {R13, R15, R14, R16}
__device__ unsigned g_RC[2][N_EDGES];  // packed (row | col<<16) per GSO
__device__ unsigned g_bm1[BM_WORDS];
__device__ unsigned g_bm2[BM_WORDS];
__device__ float g_D[17][4][64];
__device__ float g_sig[5];
__device__ int g_count;             // returns to 0 at each barrier
__device__ volatile int g_gen;      // monotonic; equality-compare only

__constant__ int c_VEC_ID[5][5] = {
    {0, 1, 3, 2, 6},
    {1, 3, 7, 4, 9},
    {3, 7, 13, 8, 14},
    {2, 5, 10, 6, 12},
    {6, 11, 15, 12, 16}};
// pool slots: CL1.xy, CL2.xyzw, CL3p0.xy, CL3s0, CL3p1.xy, CL3s1, CL4.xyzw
__constant__ int c_SVID[16] = {1, 2, 3, 5, 4, 6, 7, 11, 10, 8, 12, 9, 13, 15, 14, 16};
__constant__ int c_PC2A[4] = {0, 1, 3, 4};  // early-epilogue pc2 (si in {0,1,0,3})

__device__ __forceinline__ void red1(float* p, float a) {
    asm volatile("red.global.add.f32 [%0], %1;" :: "l"(p), "f"(a) : "memory");
}
__device__ __forceinline__ void red2(float* p, float a, float b) {
    asm volatile("red.global.add.v2.f32 [%0], {%1,%2};" :: "l"(p), "f"(a), "f"(b) : "memory");
}

__device__ __forceinline__ void barrier_arrive(int target) {
    __syncthreads();
    if (threadIdx.x == 0) {
        __threadfence();
        int gen = g_gen;
        if (atomicAdd(&g_count, 1) == target - 1) {
            g_count = 0;
            __threadfence();
            g_gen = gen + 1;
        }
    }
}
__device__ __forceinline__ void barrier_wait(int target) {
    __syncthreads();
    if (threadIdx.x == 0) {
        __threadfence();
        int gen = g_gen;
        if (atomicAdd(&g_count, 1) == target - 1) {
            g_count = 0;
            __threadfence();
            g_gen = gen + 1;
        } else {
            while (g_gen == gen) { }
        }
    }
    __syncthreads();
}

// Full epilogue unit for one (b, pc2): T[si] in smem, then out += T @ W2[pc2].
__device__ __forceinline__ void epi_unit(
    int b, int pc2, const float* __restrict__ x,
    const float* __restrict__ W1, const float* __restrict__ b1,
    const float* __restrict__ W2, float* __restrict__ out, float* pool) {
    int e2 = pc2 / 3, k2 = pc2 % 3;
    int si = (k2 == 0) ? 0 : (e2 * 2 + k2);
    float sg = (si == 0) ? 1.0f : __ldg(&g_sig[si]);
    int g = threadIdx.x & 127, fo = threadIdx.x >> 7;  // 8 f-groups
    float* Tl = pool + 1024;
    float acc = 0.f;
#pragma unroll
    for (int pc1 = 0; pc1 < 6; pc1++) {
        int e1 = pc1 / 3, k1 = pc1 % 3;
        int pi = (k1 == 0) ? 0 : (e1 * 2 + k1);
        int vid = c_VEC_ID[si][pi];
        const float* Dp = vid ? &g_D[vid][b][0] : (x + (size_t)b * N_NODES * 64);
        const float* Wp = W1 + (size_t)pc1 * 64 * 128;
#pragma unroll
        for (int i = 0; i < 8; i++) {
            int f = fo * 8 + i;
            acc += __ldg(Dp + f) * __ldg(Wp + (size_t)f * 128 + g);
        }
    }
    pool[fo * 128 + g] = acc;
    __syncthreads();
    if (fo == 0) {
        float s = sg * __ldg(b1 + g);
#pragma unroll
        for (int i = 0; i < 8; i++) s += pool[i * 128 + g];
        Tl[g] = s;
    }
    __syncthreads();
    const float* Wp2 = W2 + (size_t)pc2 * 128 * 128;
    float acc2 = 0.f;
#pragma unroll
    for (int i = 0; i < 16; i++) {
        int f = fo * 16 + i;
        acc2 += Tl[f] * __ldg(Wp2 + (size_t)f * 128 + g);
    }
    __syncthreads();
    pool[fo * 128 + g] = acc2;
    __syncthreads();
    if (fo == 0) {
        float s = 0.f;
#pragma unroll
        for (int i = 0; i < 8; i++) s += pool[i * 128 + g];
        atomicAdd(out + (size_t)b * 128 + g, s);
    }
}

__global__ void __launch_bounds__(NT, 1)
fused_kernel(const int* __restrict__ eidx, const float* __restrict__ evals,
             const float* __restrict__ x,
             const float* __restrict__ W1, const float* __restrict__ b1,
             const float* __restrict__ W2, const float* __restrict__ b2,
             float* __restrict__ out) {
    __shared__ __align__(16) float pool[1920];
    __shared__ unsigned sbm[BM_WORDS];

    const int tid = threadIdx.x;
    const int blk = blockIdx.x;
    const float4 z4 = make_float4(0.f, 0.f, 0.f, 0.f);

    // Balanced contiguous quad range; each thread owns quads t0=tid, t1=tid+1024.
    const int qstart = blk * QPB;
    const int qcount = min(QPB, 2 * QUADS - qstart);
    const bool h0 = tid < qcount;
    const bool h1 = tid + NT < qcount;
    const int q0 = qstart + tid;
    const int q1 = qstart + tid + NT;
    const int g0 = q0 >= QUADS, j0 = q0 - g0 * QUADS;
    const int g1 = q1 >= QUADS, j1 = q1 - g1 * QUADS;

    // ---- P1: lvl1 (parent = e_0) + build bm1 + pack RC; block 0 inits out=b2 ----
    if (blk == 0 && tid < 512)
        out[tid] = __ldg(b2 + (tid & 127));
    {
        int4 r0, c0, r1, c1;
        if (h0) {
            const int* eb = eidx + (size_t)g0 * 2 * N_EDGES;
            r0 = __ldg((const int4*)eb + j0);
            c0 = __ldg((const int4*)(eb + N_EDGES) + j0);
        }
        if (h1) {
            const int* eb = eidx + (size_t)g1 * 2 * N_EDGES;
            r1 = __ldg((const int4*)eb + j1);
            c1 = __ldg((const int4*)(eb + N_EDGES) + j1);
        }
        if (h0) {
            uint4 p;
            p.x = (unsigned)r0.x | ((unsigned)c0.x << 16);
            p.y = (unsigned)r0.y | ((unsigned)c0.y << 16);
            p.z = (unsigned)r0.z | ((unsigned)c0.z << 16);
            p.w = (unsigned)r0.w | ((unsigned)c0.w << 16);
            ((uint4*)g_RC[g0])[j0] = p;
            if (r0.x == 0 || r0.y == 0 || r0.z == 0 || r0.w == 0) {
                const int ri[4] = {r0.x, r0.y, r0.z, r0.w};
                const int ci[4] = {c0.x, c0.y, c0.z, c0.w};
                float* base = (float*)g_CL1 + g0;
#pragma unroll
                for (int i = 0; i < 4; i++)
                    if (ri[i] == 0) {
                        float v = __ldg(evals + (size_t)g0 * N_EDGES + j0 * 4 + i);
                        atomicAdd(base + ci[i] * 2, v);
                        atomicOr(&g_bm1[ci[i] >> 5], 1u << (ci[i] & 31));
                    }
            }
        }
        if (h1) {
            uint4 p;
            p.x = (unsigned)r1.x | ((unsigned)c1.x << 16);
            p.y = (unsigned)r1.y | ((unsigned)c1.y << 16);
            p.z = (unsigned)r1.z | ((unsigned)c1.z << 16);
            p.w = (unsigned)r1.w | ((unsigned)c1.w << 16);
            ((uint4*)g_RC[g1])[j1] = p;
            if (r1.x == 0 || r1.y == 0 || r1.z == 0 || r1.w == 0) {
                const int ri[4] = {r1.x, r1.y, r1.z, r1.w};
                const int ci[4] = {c1.x, c1.y, c1.z, c1.w};
                float* base = (float*)g_CL1 + g1;
#pragma unroll
                for (int i = 0; i < 4; i++)
                    if (ri[i] == 0) {
                        float v = __ldg(evals + (size_t)g1 * N_EDGES + j1 * 4 + i);
                        atomicAdd(base + ci[i] * 2, v);
                        atomicOr(&g_bm1[ci[i] >> 5], 1u << (ci[i] & 31));
                    }
            }
        }
    }
    barrier_wait(NB);

    // ---- P2: lvl2 (bm1-filtered; RC stream) + build bm2 ----
    if (tid < BM_WORDS) sbm[tid] = __ldg(&g_bm1[tid]);
    __syncthreads();
    {
        uint4 rc0, rc1;
        if (h0) rc0 = __ldg((const uint4*)g_RC[g0] + j0);
        if (h1) rc1 = __ldg((const uint4*)g_RC[g1] + j1);
        unsigned pk0[4] = {rc0.x, rc0.y, rc0.z, rc0.w};
        unsigned pk1[4] = {rc1.x, rc1.y, rc1.z, rc1.w};
        unsigned m0 = 0, m1 = 0;
#pragma unroll
        for (int i = 0; i < 4; i++) {
            unsigned rr = pk0[i] & 0xffffu;
            if (h0) m0 |= (sbm[rr >> 5] >> (rr & 31)) & 1u ? (1u << i) : 0u;
            unsigned ss = pk1[i] & 0xffffu;
            if (h1) m1 |= (sbm[ss >> 5] >> (ss & 31)) & 1u ? (1u << i) : 0u;
        }
        if (m0) {
            float* base = (float*)g_CL2 + 2 * g0;
#pragma unroll
            for (int i = 0; i < 4; i++)
                if (m0 & (1u << i)) {
                    float2 qv = __ldg(g_CL1 + (pk0[i] & 0xffffu));
                    if ((qv.x != 0.f) | (qv.y != 0.f)) {
                        unsigned cc = pk0[i] >> 16;
                        float v = __ldg(evals + (size_t)g0 * N_EDGES + j0 * 4 + i);
                        red2(base + cc * 4, v * qv.x, v * qv.y);
                        atomicOr(&g_bm2[cc >> 5], 1u << (cc & 31));
                    }
                }
        }
        if (m1) {
            float* base = (float*)g_CL2 + 2 * g1;
#pragma unroll
            for (int i = 0; i < 4; i++)
                if (m1 & (1u << i)) {
                    float2 qv = __ldg(g_CL1 + (pk1[i] & 0xffffu));
                    if ((qv.x != 0.f) | (qv.y != 0.f)) {
                        unsigned cc = pk1[i] >> 16;
                        float v = __ldg(evals + (size_t)g1 * N_EDGES + j1 * 4 + i);
                        red2(base + cc * 4, v * qv.x, v * qv.y);
                        atomicOr(&g_bm2[cc >> 5], 1u << (cc & 31));
                    }
                }
        }
    }
    barrier_wait(NB);

    // ---- P3: lvl3 (bm2-filtered; hoisted gathers; red2 pair + red1 scalar) ----
    if (tid < BM_WORDS) sbm[tid] = __ldg(&g_bm2[tid]);
    __syncthreads();
    {
        uint4 rc0, rc1;
        if (h0) rc0 = __ldg((const uint4*)g_RC[g0] + j0);
        if (h1) rc1 = __ldg((const uint4*)g_RC[g1] + j1);
        unsigned pk0[4] = {rc0.x, rc0.y, rc0.z, rc0.w};
        unsigned pk1[4] = {rc1.x, rc1.y, rc1.z, rc1.w};
        unsigned m0 = 0, m1 = 0;
#pragma unroll
        for (int i = 0; i < 4; i++) {
            unsigned rr = pk0[i] & 0xffffu;
            if (h0) m0 |= (sbm[rr >> 5] >> (rr & 31)) & 1u ? (1u << i) : 0u;
            unsigned ss = pk1[i] & 0xffffu;
            if (h1) m1 |= (sbm[ss >> 5] >> (ss & 31)) & 1u ? (1u << i) : 0u;
        }
        if (m0 | m1) {
            float4 v0, v1;
            if (m0) v0 = __ldg((const float4*)(evals + (size_t)g0 * N_EDGES) + j0);
            if (m1) v1 = __ldg((const float4*)(evals + (size_t)g1 * N_EDGES) + j1);
            float4 qa[4], qb[4];
#pragma unroll
            for (int i = 0; i < 4; i++)
                qa[i] = (m0 & (1u << i)) ? __ldg(g_CL2 + (pk0[i] & 0xffffu)) : z4;
#pragma unroll
            for (int i = 0; i < 4; i++)
                qb[i] = (m1 & (1u << i)) ? __ldg(g_CL2 + (pk1[i] & 0xffffu)) : z4;
            const float vv0[4] = {v0.x, v0.y, v0.z, v0.w};
            const float vv1[4] = {v1.x, v1.y, v1.z, v1.w};
#pragma unroll
            for (int i = 0; i < 4; i++)
                if (m0 & (1u << i)) {
                    float p0 = qa[i].x;                 // R3 parent
                    float p1 = g0 ? qa[i].z : qa[i].y;  // R4 / R5 parent
                    float p2 = qa[i].w;                 // R6 parent
                    unsigned cc = pk0[i] >> 16;
                    if ((p0 != 0.f) | (p2 != 0.f))
                        red2((float*)&g_CL3p[g0][cc], vv0[i] * p0, vv0[i] * p2);
                    if (p1 != 0.f)
                        red1(&g_CL3s[g0][cc], vv0[i] * p1);
                }
#pragma unroll
            for (int i = 0; i < 4; i++)
                if (m1 & (1u << i)) {
                    float p0 = qb[i].x;
                    float p1 = g1 ? qb[i].z : qb[i].y;
                    float p2 = qb[i].w;
                    unsigned cc = pk1[i] >> 16;
                    if ((p0 != 0.f) | (p2 != 0.f))
                        red2((float*)&g_CL3p[g1][cc], vv1[i] * p0, vv1[i] * p2);
                    if (p1 != 0.f)
                        red1(&g_CL3s[g1][cc], vv1[i] * p1);
                }
        }
    }
    barrier_wait(NB);

    // ---- P4: lvl4 (dense; hoisted float2 gathers from packed 80KB arrays),
    //          then dot of the 12 final slots + sigma + zero CL1/CL2/bm ----
    {
        uint4 rc0, rc1;
        float4 v0, v1;
        if (h0) {
            rc0 = __ldg((const uint4*)g_RC[g0] + j0);
            v0 = __ldg((const float4*)(evals + (size_t)g0 * N_EDGES) + j0);
        }
        if (h1) {
            rc1 = __ldg((const uint4*)g_RC[g1] + j1);
            v1 = __ldg((const float4*)(evals + (size_t)g1 * N_EDGES) + j1);
        }
        const float2* s0 = g_CL3p[g0];
        const float2* s1 = g_CL3p[g1];
        const unsigned pk0[4] = {rc0.x, rc0.y, rc0.z, rc0.w};
        const unsigned pk1[4] = {rc1.x, rc1.y, rc1.z, rc1.w};
        float2 ga[4], gb[4];
#pragma unroll
        for (int i = 0; i < 4; i++)
            ga[i] = h0 ? __ldg(s0 + (pk0[i] & 0xffffu)) : make_float2(0.f, 0.f);
#pragma unroll
        for (int i = 0; i < 4; i++)
            gb[i] = h1 ? __ldg(s1 + (pk1[i] & 0xffffu)) : make_float2(0.f, 0.f);
        const float vv0[4] = {v0.x, v0.y, v0.z, v0.w};
        const float vv1[4] = {v1.x, v1.y, v1.z, v1.w};
        float* base0 = (float*)g_CL4 + 2 * g0;
        float* base1 = (float*)g_CL4 + 2 * g1;
#pragma unroll
        for (int i = 0; i < 4; i++)
            if (((ga[i].x != 0.f) | (ga[i].y != 0.f)) && h0)
                red2(base0 + (pk0[i] >> 16) * 4, vv0[i] * ga[i].x, vv0[i] * ga[i].y);
#pragma unroll
        for (int i = 0; i < 4; i++)
            if (((gb[i].x != 0.f) | (gb[i].y != 0.f)) && h1)
                red2(base1 + (pk1[i] >> 16) * 4, vv1[i] * gb[i].x, vv1[i] * gb[i].y);
    }
    {
        int n0 = blk * DC;
        int lim = min(DC, N_NODES - n0);
        if (tid < lim) {
            int gn = n0 + tid;
            float2 a = __ldg(g_CL1 + gn);
            float4 c2 = __ldg(g_CL2 + gn);
            float2 p0 = __ldg(&g_CL3p[0][gn]);
            float s0v = __ldg(&g_CL3s[0][gn]);
            float2 p1 = __ldg(&g_CL3p[1][gn]);
            float s1v = __ldg(&g_CL3s[1][gn]);
            pool[0 * DC + tid] = a.x;   pool[1 * DC + tid] = a.y;
            pool[2 * DC + tid] = c2.x;  pool[3 * DC + tid] = c2.y;
            pool[4 * DC + tid] = c2.z;  pool[5 * DC + tid] = c2.w;
            pool[6 * DC + tid] = p0.x;  pool[7 * DC + tid] = p0.y;
            pool[8 * DC + tid] = s0v;
            pool[9 * DC + tid] = p1.x;  pool[10 * DC + tid] = p1.y;
            pool[11 * DC + tid] = s1v;
            // restore zeros (after loads; same thread = program order);
            // CL1/CL2 are not read by any other block in P4
            g_CL1[gn] = make_float2(0.f, 0.f);
            g_CL2[gn] = z4;
        }
        if (blk == 0 && tid >= 512 && tid < 512 + BM_WORDS) {
            g_bm1[tid - 512] = 0u;
            g_bm2[tid - 512] = 0u;
        }
        __syncthreads();
        if (tid < 128) {  // sigma: sig[1..4] = column sums of slots {0,2,1,5}
            const int slots[4] = {0, 2, 1, 5};
            int vi = tid >> 5, lane = tid & 31;
            float s = 0.f;
            for (int n = lane; n < lim; n += 32) s += pool[slots[vi] * DC + n];
#pragma unroll
            for (int off = 16; off; off >>= 1) s += __shfl_down_sync(0xffffffffu, s, off);
            if (lane == 0) atomicAdd(&g_sig[vi + 1], s);
        }
        int f = tid & 63;
        int bb = (tid >> 6) & 3;
        int vg = tid >> 8;  // 0..3, 3 slots each
        float a0 = 0.f, a1 = 0.f, a2 = 0.f;
        const float* xb = x + ((size_t)bb * N_NODES + n0) * 64 + f;
        const float* rsv = pool + vg * 3 * DC;
        for (int nn = 0; nn < lim; nn++) {
            float xv = __ldg(xb + (size_t)nn * 64);
            a0 += rsv[0 * DC + nn] * xv;
            a1 += rsv[1 * DC + nn] * xv;
            a2 += rsv[2 * DC + nn] * xv;
        }
        atomicAdd(&g_D[c_SVID[vg * 3 + 0]][bb][f], a0);
        atomicAdd(&g_D[c_SVID[vg * 3 + 1]][bb][f], a1);
        atomicAdd(&g_D[c_SVID[vg * 3 + 2]][bb][f], a2);
    }
    barrier_wait(NB);

    // ---- P5': blocks 0..15 early epilogue (pc2 in {0,1,3,4});
    //           blocks 16..147 dot of the 4 CL4 slots + zero CL3/CL4 ----
    if (blk < 16) {
        epi_unit(blk & 3, c_PC2A[blk >> 2], x, W1, b1, W2, out, pool);
    } else {
        int lblk = blk - 16;
        int n0 = lblk * DC5;
        int lim = min(DC5, N_NODES - n0);
        if (lim > 0 && tid < lim) {
            int gn = n0 + tid;
            float4 c4 = __ldg(g_CL4 + gn);
            pool[0 * DC5 + tid] = c4.x; pool[1 * DC5 + tid] = c4.y;
            pool[2 * DC5 + tid] = c4.z; pool[3 * DC5 + tid] = c4.w;
            g_CL4[gn] = z4;
            g_CL3p[0][gn] = make_float2(0.f, 0.f);
            g_CL3p[1][gn] = make_float2(0.f, 0.f);
            g_CL3s[0][gn] = 0.f;
            g_CL3s[1][gn] = 0.f;
        }
        __syncthreads();
        if (lim > 0) {
            int f = tid & 63;
            int bb = (tid >> 6) & 3;
            int vg = tid >> 8;  // 0..3, 1 slot each
            float a0 = 0.f;
            const float* xb = x + ((size_t)bb * N_NODES + n0) * 64 + f;
            const float* rsv = pool + vg * DC5;
            for (int nn = 0; nn < lim; nn++)
                a0 += rsv[nn] * __ldg(xb + (size_t)nn * 64);
            atomicAdd(&g_D[c_SVID[12 + vg]][bb][f], a0);
        }
    }
    if (blk >= 8) { barrier_arrive(NB); return; }
    barrier_wait(NB);

    // ---- PE2: blocks 0..7 = (b, pc2 in {2,5}) -> T[2]/T[4] + out ----
    epi_unit(blk & 3, (blk >> 2) ? 5 : 2, x, W1, b1, W2, out, pool);
    barrier_wait(8);
    // zero D and sig (read in epilogue; safe only after the 8-block barrier)
    for (int i = blk * NT + tid; i < 17 * 4 * 64; i += 8 * NT) (&g_D[0][0][0])[i] = 0.f;
    if (blk == 0 && tid < 5) g_sig[tid] = 0.f;
}

extern "C" void kernel_launch(void* const* d_in, const int* in_sizes, int n_in,
                              void* d_out, int out_size) {
    const float* x = nullptr;
    const int* eidx = nullptr;
    const float* evals = nullptr;
    const float *W1 = nullptr, *b1 = nullptr, *W2 = nullptr, *b2 = nullptr;
    for (int i = 0; i < n_in; i++) {
        switch (in_sizes[i]) {
            case 2560000: x = (const float*)d_in[i]; break;
            case 1280000: eidx = (const int*)d_in[i]; break;
            case 640000:  evals = (const float*)d_in[i]; break;
            case 49152:   W1 = (const float*)d_in[i]; break;
            case 98304:   W2 = (const float*)d_in[i]; break;
            case 128:
                if (!b1) b1 = (const float*)d_in[i];
                else b2 = (const float*)d_in[i];
                break;
        }
    }
    float* out = (float*)d_out;
    fused_kernel<<<NB, NT>>>(eidx, evals, x, W1, b1, W2, b2, out);
}

// round 15
// speedup vs baseline: 1.0054x; 1.0054x over previous
#include <cuda_runtime.h>

#define N_NODES 10000
#define N_EDGES 320000
#define QUADS (N_EDGES / 4)
#define NB 148
#define NT 1024
#define NTHR (NB * NT)
#define BM_WORDS 320
#define DC 68       // P4 dot chunk: 148 blocks x 68 >= 10000
#define DC5 76      // P5' dot chunk: 132 blocks x 76 >= 10000
#define QPB 1082    // quads per block: 148*1082 >= 2*QUADS (last block partial)

// INVARIANT: accumulated scratch (CL*, bm*, D, sig) is ZERO at kernel entry
// and restored to ZERO before exit. L1-cached __ldg of data written earlier in
// this launch is safe: L1 is flushed at launch boundaries, global stores and
// atomics don't allocate in L1, and no array is regular-loaded before its
// producer phase's barrier. Edge coords are held in REGISTERS across phases
// (each thread owns the same two quads in every phase) — no g_RC array.
__device__ float2 g_CL1[N_NODES];      // {R1, R2}
__device__ float4 g_CL2[N_NODES];      // {R3, R5, R4, R6}
__device__ float2 g_CL3p[2][N_NODES];  // GSO0: {R7, R11}; GSO1: {R8, R12}  (lvl4 gathers)
__device__ float  g_CL3s[2][N_NODES];  // GSO0: R10;       GSO1: R9        (dot only)
__device__ float4 g_CL4[N_NODES];      // {R13, R15, R14, R16}
__device__ unsigned g_bm1[BM_WORDS];
__device__ unsigned g_bm2[BM_WORDS];
__device__ float g_D[17][4][64];
__device__ float g_sig[5];
__device__ int g_count;             // returns to 0 at each barrier
__device__ volatile int g_gen;      // monotonic; equality-compare only

__constant__ int c_VEC_ID[5][5] = {
    {0, 1, 3, 2, 6},
    {1, 3, 7, 4, 9},
    {3, 7, 13, 8, 14},
    {2, 5, 10, 6, 12},
    {6, 11, 15, 12, 16}};
// pool slots: CL1.xy, CL2.xyzw, CL3p0.xy, CL3s0, CL3p1.xy, CL3s1, CL4.xyzw
__constant__ int c_SVID[16] = {1, 2, 3, 5, 4, 6, 7, 11, 10, 8, 12, 9, 13, 15, 14, 16};
__constant__ int c_PC2A[4] = {0, 1, 3, 4};  // early-epilogue pc2 (si in {0,1,0,3})

__device__ __forceinline__ void red1(float* p, float a) {
    asm volatile("red.global.add.f32 [%0], %1;" :: "l"(p), "f"(a) : "memory");
}
__device__ __forceinline__ void red2(float* p, float a, float b) {
    asm volatile("red.global.add.v2.f32 [%0], {%1,%2};" :: "l"(p), "f"(a), "f"(b) : "memory");
}

__device__ __forceinline__ void barrier_arrive(int target) {
    __syncthreads();
    if (threadIdx.x == 0) {
        __threadfence();
        int gen = g_gen;
        if (atomicAdd(&g_count, 1) == target - 1) {
            g_count = 0;
            __threadfence();
            g_gen = gen + 1;
        }
    }
}
__device__ __forceinline__ void barrier_wait(int target) {
    __syncthreads();
    if (threadIdx.x == 0) {
        __threadfence();
        int gen = g_gen;
        if (atomicAdd(&g_count, 1) == target - 1) {
            g_count = 0;
            __threadfence();
            g_gen = gen + 1;
        } else {
            while (g_gen == gen) { }
        }
    }
    __syncthreads();
}

// Full epilogue unit for one (b, pc2): T[si] in smem, then out += T @ W2[pc2].
__device__ __forceinline__ void epi_unit(
    int b, int pc2, const float* __restrict__ x,
    const float* __restrict__ W1, const float* __restrict__ b1,
    const float* __restrict__ W2, float* __restrict__ out, float* pool) {
    int e2 = pc2 / 3, k2 = pc2 % 3;
    int si = (k2 == 0) ? 0 : (e2 * 2 + k2);
    float sg = (si == 0) ? 1.0f : __ldg(&g_sig[si]);
    int g = threadIdx.x & 127, fo = threadIdx.x >> 7;  // 8 f-groups
    float* Tl = pool + 1024;
    float acc = 0.f;
#pragma unroll
    for (int pc1 = 0; pc1 < 6; pc1++) {
        int e1 = pc1 / 3, k1 = pc1 % 3;
        int pi = (k1 == 0) ? 0 : (e1 * 2 + k1);
        int vid = c_VEC_ID[si][pi];
        const float* Dp = vid ? &g_D[vid][b][0] : (x + (size_t)b * N_NODES * 64);
        const float* Wp = W1 + (size_t)pc1 * 64 * 128;
#pragma unroll
        for (int i = 0; i < 8; i++) {
            int f = fo * 8 + i;
            acc += __ldg(Dp + f) * __ldg(Wp + (size_t)f * 128 + g);
        }
    }
    pool[fo * 128 + g] = acc;
    __syncthreads();
    if (fo == 0) {
        float s = sg * __ldg(b1 + g);
#pragma unroll
        for (int i = 0; i < 8; i++) s += pool[i * 128 + g];
        Tl[g] = s;
    }
    __syncthreads();
    const float* Wp2 = W2 + (size_t)pc2 * 128 * 128;
    float acc2 = 0.f;
#pragma unroll
    for (int i = 0; i < 16; i++) {
        int f = fo * 16 + i;
        acc2 += Tl[f] * __ldg(Wp2 + (size_t)f * 128 + g);
    }
    __syncthreads();
    pool[fo * 128 + g] = acc2;
    __syncthreads();
    if (fo == 0) {
        float s = 0.f;
#pragma unroll
        for (int i = 0; i < 8; i++) s += pool[i * 128 + g];
        atomicAdd(out + (size_t)b * 128 + g, s);
    }
}

__global__ void __launch_bounds__(NT, 1)
fused_kernel(const int* __restrict__ eidx, const float* __restrict__ evals,
             const float* __restrict__ x,
             const float* __restrict__ W1, const float* __restrict__ b1,
             const float* __restrict__ W2, const float* __restrict__ b2,
             float* __restrict__ out) {
    __shared__ __align__(16) float pool[1920];
    __shared__ unsigned sbm[BM_WORDS];

    const int tid = threadIdx.x;
    const int blk = blockIdx.x;
    const float4 z4 = make_float4(0.f, 0.f, 0.f, 0.f);

    // Balanced contiguous quad range; each thread owns quads t0=tid, t1=tid+1024
    // in EVERY phase, so their packed coords live in registers for the kernel.
    const int qstart = blk * QPB;
    const int qcount = min(QPB, 2 * QUADS - qstart);
    const bool h0 = tid < qcount;
    const bool h1 = tid + NT < qcount;
    const int q0 = qstart + tid;
    const int q1 = qstart + tid + NT;
    const int g0 = q0 >= QUADS, j0 = q0 - g0 * QUADS;
    const int g1 = q1 >= QUADS, j1 = q1 - g1 * QUADS;

    uint4 rc0 = make_uint4(0u, 0u, 0u, 0u);   // persistent packed row|col<<16
    uint4 rc1 = make_uint4(0u, 0u, 0u, 0u);

    // ---- P1: lvl1 (parent = e_0) + build bm1 + pack coords; block 0 inits out=b2 ----
    if (blk == 0 && tid < 512)
        out[tid] = __ldg(b2 + (tid & 127));
    {
        int4 r0, c0, r1, c1;
        if (h0) {
            const int* eb = eidx + (size_t)g0 * 2 * N_EDGES;
            r0 = __ldg((const int4*)eb + j0);
            c0 = __ldg((const int4*)(eb + N_EDGES) + j0);
        }
        if (h1) {
            const int* eb = eidx + (size_t)g1 * 2 * N_EDGES;
            r1 = __ldg((const int4*)eb + j1);
            c1 = __ldg((const int4*)(eb + N_EDGES) + j1);
        }
        if (h0) {
            rc0.x = (unsigned)r0.x | ((unsigned)c0.x << 16);
            rc0.y = (unsigned)r0.y | ((unsigned)c0.y << 16);
            rc0.z = (unsigned)r0.z | ((unsigned)c0.z << 16);
            rc0.w = (unsigned)r0.w | ((unsigned)c0.w << 16);
            if (r0.x == 0 || r0.y == 0 || r0.z == 0 || r0.w == 0) {
                const int ri[4] = {r0.x, r0.y, r0.z, r0.w};
                const int ci[4] = {c0.x, c0.y, c0.z, c0.w};
                float* base = (float*)g_CL1 + g0;
#pragma unroll
                for (int i = 0; i < 4; i++)
                    if (ri[i] == 0) {
                        float v = __ldg(evals + (size_t)g0 * N_EDGES + j0 * 4 + i);
                        atomicAdd(base + ci[i] * 2, v);
                        atomicOr(&g_bm1[ci[i] >> 5], 1u << (ci[i] & 31));
                    }
            }
        }
        if (h1) {
            rc1.x = (unsigned)r1.x | ((unsigned)c1.x << 16);
            rc1.y = (unsigned)r1.y | ((unsigned)c1.y << 16);
            rc1.z = (unsigned)r1.z | ((unsigned)c1.z << 16);
            rc1.w = (unsigned)r1.w | ((unsigned)c1.w << 16);
            if (r1.x == 0 || r1.y == 0 || r1.z == 0 || r1.w == 0) {
                const int ri[4] = {r1.x, r1.y, r1.z, r1.w};
                const int ci[4] = {c1.x, c1.y, c1.z, c1.w};
                float* base = (float*)g_CL1 + g1;
#pragma unroll
                for (int i = 0; i < 4; i++)
                    if (ri[i] == 0) {
                        float v = __ldg(evals + (size_t)g1 * N_EDGES + j1 * 4 + i);
                        atomicAdd(base + ci[i] * 2, v);
                        atomicOr(&g_bm1[ci[i] >> 5], 1u << (ci[i] & 31));
                    }
            }
        }
    }
    barrier_wait(NB);

    // ---- P2: lvl2 (bm1-filtered; coords from registers) + build bm2 ----
    if (tid < BM_WORDS) sbm[tid] = __ldg(&g_bm1[tid]);
    __syncthreads();
    {
        unsigned pk0[4] = {rc0.x, rc0.y, rc0.z, rc0.w};
        unsigned pk1[4] = {rc1.x, rc1.y, rc1.z, rc1.w};
        unsigned m0 = 0, m1 = 0;
#pragma unroll
        for (int i = 0; i < 4; i++) {
            unsigned rr = pk0[i] & 0xffffu;
            if (h0) m0 |= (sbm[rr >> 5] >> (rr & 31)) & 1u ? (1u << i) : 0u;
            unsigned ss = pk1[i] & 0xffffu;
            if (h1) m1 |= (sbm[ss >> 5] >> (ss & 31)) & 1u ? (1u << i) : 0u;
        }
        if (m0) {
            float* base = (float*)g_CL2 + 2 * g0;
#pragma unroll
            for (int i = 0; i < 4; i++)
                if (m0 & (1u << i)) {
                    float2 qv = __ldg(g_CL1 + (pk0[i] & 0xffffu));
                    if ((qv.x != 0.f) | (qv.y != 0.f)) {
                        unsigned cc = pk0[i] >> 16;
                        float v = __ldg(evals + (size_t)g0 * N_EDGES + j0 * 4 + i);
                        red2(base + cc * 4, v * qv.x, v * qv.y);
                        atomicOr(&g_bm2[cc >> 5], 1u << (cc & 31));
                    }
                }
        }
        if (m1) {
            float* base = (float*)g_CL2 + 2 * g1;
#pragma unroll
            for (int i = 0; i < 4; i++)
                if (m1 & (1u << i)) {
                    float2 qv = __ldg(g_CL1 + (pk1[i] & 0xffffu));
                    if ((qv.x != 0.f) | (qv.y != 0.f)) {
                        unsigned cc = pk1[i] >> 16;
                        float v = __ldg(evals + (size_t)g1 * N_EDGES + j1 * 4 + i);
                        red2(base + cc * 4, v * qv.x, v * qv.y);
                        atomicOr(&g_bm2[cc >> 5], 1u << (cc & 31));
                    }
                }
        }
    }
    barrier_wait(NB);

    // ---- P3: lvl3 (bm2-filtered; coords from registers; hoisted gathers) ----
    if (tid < BM_WORDS) sbm[tid] = __ldg(&g_bm2[tid]);
    __syncthreads();
    {
        unsigned pk0[4] = {rc0.x, rc0.y, rc0.z, rc0.w};
        unsigned pk1[4] = {rc1.x, rc1.y, rc1.z, rc1.w};
        unsigned m0 = 0, m1 = 0;
#pragma unroll
        for (int i = 0; i < 4; i++) {
            unsigned rr = pk0[i] & 0xffffu;
            if (h0) m0 |= (sbm[rr >> 5] >> (rr & 31)) & 1u ? (1u << i) : 0u;
            unsigned ss = pk1[i] & 0xffffu;
            if (h1) m1 |= (sbm[ss >> 5] >> (ss & 31)) & 1u ? (1u << i) : 0u;
        }
        if (m0 | m1) {
            float4 v0, v1;
            if (m0) v0 = __ldg((const float4*)(evals + (size_t)g0 * N_EDGES) + j0);
            if (m1) v1 = __ldg((const float4*)(evals + (size_t)g1 * N_EDGES) + j1);
            float4 qa[4], qb[4];
#pragma unroll
            for (int i = 0; i < 4; i++)
                qa[i] = (m0 & (1u << i)) ? __ldg(g_CL2 + (pk0[i] & 0xffffu)) : z4;
#pragma unroll
            for (int i = 0; i < 4; i++)
                qb[i] = (m1 & (1u << i)) ? __ldg(g_CL2 + (pk1[i] & 0xffffu)) : z4;
            const float vv0[4] = {v0.x, v0.y, v0.z, v0.w};
            const float vv1[4] = {v1.x, v1.y, v1.z, v1.w};
#pragma unroll
            for (int i = 0; i < 4; i++)
                if (m0 & (1u << i)) {
                    float p0 = qa[i].x;                 // R3 parent
                    float p1 = g0 ? qa[i].z : qa[i].y;  // R4 / R5 parent
                    float p2 = qa[i].w;                 // R6 parent
                    unsigned cc = pk0[i] >> 16;
                    if ((p0 != 0.f) | (p2 != 0.f))
                        red2((float*)&g_CL3p[g0][cc], vv0[i] * p0, vv0[i] * p2);
                    if (p1 != 0.f)
                        red1(&g_CL3s[g0][cc], vv0[i] * p1);
                }
#pragma unroll
            for (int i = 0; i < 4; i++)
                if (m1 & (1u << i)) {
                    float p0 = qb[i].x;
                    float p1 = g1 ? qb[i].z : qb[i].y;
                    float p2 = qb[i].w;
                    unsigned cc = pk1[i] >> 16;
                    if ((p0 != 0.f) | (p2 != 0.f))
                        red2((float*)&g_CL3p[g1][cc], vv1[i] * p0, vv1[i] * p2);
                    if (p1 != 0.f)
                        red1(&g_CL3s[g1][cc], vv1[i] * p1);
                }
        }
    }
    barrier_wait(NB);

    // ---- P4: lvl4 (dense; coords from registers; hoisted float2 gathers),
    //          then dot of the 12 final slots + sigma + zero CL1/CL2/bm ----
    {
        float4 v0, v1;
        if (h0) v0 = __ldg((const float4*)(evals + (size_t)g0 * N_EDGES) + j0);
        if (h1) v1 = __ldg((const float4*)(evals + (size_t)g1 * N_EDGES) + j1);
        const float2* s0 = g_CL3p[g0];
        const float2* s1 = g_CL3p[g1];
        const unsigned pk0[4] = {rc0.x, rc0.y, rc0.z, rc0.w};
        const unsigned pk1[4] = {rc1.x, rc1.y, rc1.z, rc1.w};
        float2 ga[4], gb[4];
#pragma unroll
        for (int i = 0; i < 4; i++)
            ga[i] = h0 ? __ldg(s0 + (pk0[i] & 0xffffu)) : make_float2(0.f, 0.f);
#pragma unroll
        for (int i = 0; i < 4; i++)
            gb[i] = h1 ? __ldg(s1 + (pk1[i] & 0xffffu)) : make_float2(0.f, 0.f);
        const float vv0[4] = {v0.x, v0.y, v0.z, v0.w};
        const float vv1[4] = {v1.x, v1.y, v1.z, v1.w};
        float* base0 = (float*)g_CL4 + 2 * g0;
        float* base1 = (float*)g_CL4 + 2 * g1;
#pragma unroll
        for (int i = 0; i < 4; i++)
            if (((ga[i].x != 0.f) | (ga[i].y != 0.f)) && h0)
                red2(base0 + (pk0[i] >> 16) * 4, vv0[i] * ga[i].x, vv0[i] * ga[i].y);
#pragma unroll
        for (int i = 0; i < 4; i++)
            if (((gb[i].x != 0.f) | (gb[i].y != 0.f)) && h1)
                red2(base1 + (pk1[i] >> 16) * 4, vv1[i] * gb[i].x, vv1[i] * gb[i].y);
    }
    {
        int n0 = blk * DC;
        int lim = min(DC, N_NODES - n0);
        if (tid < lim) {
            int gn = n0 + tid;
            float2 a = __ldg(g_CL1 + gn);
            float4 c2 = __ldg(g_CL2 + gn);
            float2 p0 = __ldg(&g_CL3p[0][gn]);
            float s0v = __ldg(&g_CL3s[0][gn]);
            float2 p1 = __ldg(&g_CL3p[1][gn]);
            float s1v = __ldg(&g_CL3s[1][gn]);
            pool[0 * DC + tid] = a.x;   pool[1 * DC + tid] = a.y;
            pool[2 * DC + tid] = c2.x;  pool[3 * DC + tid] = c2.y;
            pool[4 * DC + tid] = c2.z;  pool[5 * DC + tid] = c2.w;
            pool[6 * DC + tid] = p0.x;  pool[7 * DC + tid] = p0.y;
            pool[8 * DC + tid] = s0v;
            pool[9 * DC + tid] = p1.x;  pool[10 * DC + tid] = p1.y;
            pool[11 * DC + tid] = s1v;
            // restore zeros (after loads; same thread = program order);
            // CL1/CL2 are not read by any other block in P4
            g_CL1[gn] = make_float2(0.f, 0.f);
            g_CL2[gn] = z4;
        }
        if (blk == 0 && tid >= 512 && tid < 512 + BM_WORDS) {
            g_bm1[tid - 512] = 0u;
            g_bm2[tid - 512] = 0u;
        }
        __syncthreads();
        if (tid < 128) {  // sigma: sig[1..4] = column sums of slots {0,2,1,5}
            const int slots[4] = {0, 2, 1, 5};
            int vi = tid >> 5, lane = tid & 31;
            float s = 0.f;
            for (int n = lane; n < lim; n += 32) s += pool[slots[vi] * DC + n];
#pragma unroll
            for (int off = 16; off; off >>= 1) s += __shfl_down_sync(0xffffffffu, s, off);
            if (lane == 0) atomicAdd(&g_sig[vi + 1], s);
        }
        int f = tid & 63;
        int bb = (tid >> 6) & 3;
        int vg = tid >> 8;  // 0..3, 3 slots each
        float a0 = 0.f, a1 = 0.f, a2 = 0.f;
        const float* xb = x + ((size_t)bb * N_NODES + n0) * 64 + f;
        const float* rsv = pool + vg * 3 * DC;
        for (int nn = 0; nn < lim; nn++) {
            float xv = __ldg(xb + (size_t)nn * 64);
            a0 += rsv[0 * DC + nn] * xv;
            a1 += rsv[1 * DC + nn] * xv;
            a2 += rsv[2 * DC + nn] * xv;
        }
        atomicAdd(&g_D[c_SVID[vg * 3 + 0]][bb][f], a0);
        atomicAdd(&g_D[c_SVID[vg * 3 + 1]][bb][f], a1);
        atomicAdd(&g_D[c_SVID[vg * 3 + 2]][bb][f], a2);
    }
    barrier_wait(NB);

    // ---- P5': blocks 0..15 early epilogue (pc2 in {0,1,3,4});
    //           blocks 16..147 dot of the 4 CL4 slots + zero CL3/CL4 ----
    if (blk < 16) {
        epi_unit(blk & 3, c_PC2A[blk >> 2], x, W1, b1, W2, out, pool);
    } else {
        int lblk = blk - 16;
        int n0 = lblk * DC5;
        int lim = min(DC5, N_NODES - n0);
        if (lim > 0 && tid < lim) {
            int gn = n0 + tid;
            float4 c4 = __ldg(g_CL4 + gn);
            pool[0 * DC5 + tid] = c4.x; pool[1 * DC5 + tid] = c4.y;
            pool[2 * DC5 + tid] = c4.z; pool[3 * DC5 + tid] = c4.w;
            g_CL4[gn] = z4;
            g_CL3p[0][gn] = make_float2(0.f, 0.f);
            g_CL3p[1][gn] = make_float2(0.f, 0.f);
            g_CL3s[0][gn] = 0.f;
            g_CL3s[1][gn] = 0.f;
        }
        __syncthreads();
        if (lim > 0) {
            int f = tid & 63;
            int bb = (tid >> 6) & 3;
            int vg = tid >> 8;  // 0..3, 1 slot each
            float a0 = 0.f;
            const float* xb = x + ((size_t)bb * N_NODES + n0) * 64 + f;
            const float* rsv = pool + vg * DC5;
            for (int nn = 0; nn < lim; nn++)
                a0 += rsv[nn] * __ldg(xb + (size_t)nn * 64);
            atomicAdd(&g_D[c_SVID[12 + vg]][bb][f], a0);
        }
    }
    if (blk >= 8) { barrier_arrive(NB); return; }
    barrier_wait(NB);

    // ---- PE2: blocks 0..7 = (b, pc2 in {2,5}) -> T[2]/T[4] + out ----
    epi_unit(blk & 3, (blk >> 2) ? 5 : 2, x, W1, b1, W2, out, pool);
    barrier_wait(8);
    // zero D and sig (read in epilogue; safe only after the 8-block barrier)
    for (int i = blk * NT + tid; i < 17 * 4 * 64; i += 8 * NT) (&g_D[0][0][0])[i] = 0.f;
    if (blk == 0 && tid < 5) g_sig[tid] = 0.f;
}

extern "C" void kernel_launch(void* const* d_in, const int* in_sizes, int n_in,
                              void* d_out, int out_size) {
    const float* x = nullptr;
    const int* eidx = nullptr;
    const float* evals = nullptr;
    const float *W1 = nullptr, *b1 = nullptr, *W2 = nullptr, *b2 = nullptr;
    for (int i = 0; i < n_in; i++) {
        switch (in_sizes[i]) {
            case 2560000: x = (const float*)d_in[i]; break;
            case 1280000: eidx = (const int*)d_in[i]; break;
            case 640000:  evals = (const float*)d_in[i]; break;
            case 49152:   W1 = (const float*)d_in[i]; break;
            case 98304:   W2 = (const float*)d_in[i]; break;
            case 128:
                if (!b1) b1 = (const float*)d_in[i];
                else b2 = (const float*)d_in[i];
                break;
        }
    }
    float* out = (float*)d_out;
    fused_kernel<<<NB, NT>>>(eidx, evals, x, W1, b1, W2, b2, out);
}